// round 1
// baseline (speedup 1.0000x reference)
#include <cuda_runtime.h>

// YOLO decode: for each (b,h,w,anchor) slot of a [B,45,H,W] head, emit
// [iou, x1, y1, x2, y2, kind] and a mask (iou > thresh).
//
// Parallelization: one thread per grid cell (b,h,w); each thread handles all
// 3 anchors. Channel reads are perfectly coalesced (stride-HW channel layout,
// consecutive threads -> consecutive hw). Box rows are staged through shared
// memory so the 6-float rows are written as one dense contiguous block per
// 128-thread CTA (float2 vectorized).

#define TPB 128

__global__ __launch_bounds__(TPB)
void decode_scale_kernel(const float* __restrict__ in,
                         const float* __restrict__ anchors,   // [3,2]
                         const float* __restrict__ thresh_p,  // scalar
                         float* __restrict__ boxes,           // scale base, row-major [rows,6]
                         float* __restrict__ mask,            // scale base, [rows]
                         int H, int W, float stride)
{
    __shared__ float s[TPB * 18];

    const int HW = H * W;
    const int cell = blockIdx.x * TPB + threadIdx.x;   // grid sized exactly: ncells % TPB == 0
    const int b  = cell / HW;
    const int cw = cell - b * HW;
    const int h  = cw / W;
    const int w  = cw - h * W;

    const float thr = __ldg(thresh_p);
    const float fw = (float)w;
    const float fh = (float)h;

    const float* base = in + (size_t)b * 45 * HW + cw;

    float row[3][6];

    #pragma unroll
    for (int a = 0; a < 3; ++a) {
        const float* p = base + (size_t)(a * 15) * HW;
        const float o0 = __ldg(p + 0 * (size_t)HW);
        const float o1 = __ldg(p + 1 * (size_t)HW);
        const float o2 = __ldg(p + 2 * (size_t)HW);
        const float o3 = __ldg(p + 3 * (size_t)HW);
        const float o4 = __ldg(p + 4 * (size_t)HW);

        // argmax over 10 class logits, first occurrence of max (strict >)
        float best = __ldg(p + 5 * (size_t)HW);
        int bi = 0;
        #pragma unroll
        for (int c = 1; c < 10; ++c) {
            float v = __ldg(p + (size_t)(5 + c) * HW);
            if (v > best) { best = v; bi = c; }
        }

        const float px = (fw + o1) * stride;
        const float py = (fh + o2) * stride;
        const float pw = __ldg(anchors + 2 * a + 0) * expf(o3);
        const float ph = __ldg(anchors + 2 * a + 1) * expf(o4);

        row[a][0] = o0;
        row[a][1] = px - 0.5f * pw;
        row[a][2] = py - 0.5f * ph;
        row[a][3] = px + 0.5f * pw;
        row[a][4] = py + 0.5f * ph;
        row[a][5] = (float)bi;

        mask[(size_t)cell * 3 + a] = (o0 > thr) ? 1.0f : 0.0f;
    }

    // Stage 18 floats per thread, then write 2304 contiguous floats per CTA.
    const int t = threadIdx.x;
    #pragma unroll
    for (int a = 0; a < 3; ++a)
        #pragma unroll
        for (int j = 0; j < 6; ++j)
            s[t * 18 + a * 6 + j] = row[a][j];
    __syncthreads();

    // 2304 floats = 1152 float2; 1152 / 128 = 9 per thread, fully coalesced.
    float2* ob = (float2*)(boxes + (size_t)blockIdx.x * TPB * 18);
    const float2* sb = (const float2*)s;
    #pragma unroll
    for (int k = 0; k < 9; ++k)
        ob[k * TPB + t] = sb[k * TPB + t];
}

extern "C" void kernel_launch(void* const* d_in, const int* in_sizes, int n_in,
                              void* d_out, int out_size)
{
    const float* out13 = (const float*)d_in[0];
    const float* out26 = (const float*)d_in[1];
    const float* out52 = (const float*)d_in[2];
    const float* anc13 = (const float*)d_in[3];
    const float* anc26 = (const float*)d_in[4];
    const float* anc52 = (const float*)d_in[5];
    const float* thr   = (const float*)d_in[6];

    float* out = (float*)d_out;

    const int B = 128;
    const int rows13 = B * 13 * 13 * 3;   //   64,896
    const int rows26 = B * 26 * 26 * 3;   //  259,584
    const int rows52 = B * 52 * 52 * 3;   // 1,038,336
    const int rowsTot = rows13 + rows26 + rows52;  // 1,362,816

    float* boxes = out;                       // [rowsTot, 6]
    float* mask  = out + (size_t)rowsTot * 6; // [rowsTot]

    // scale 13, stride 32
    {
        int ncells = B * 13 * 13;
        decode_scale_kernel<<<ncells / TPB, TPB>>>(
            out13, anc13, thr, boxes, mask, 13, 13, 32.0f);
    }
    // scale 26, stride 16
    {
        int ncells = B * 26 * 26;
        decode_scale_kernel<<<ncells / TPB, TPB>>>(
            out26, anc26, thr,
            boxes + (size_t)rows13 * 6, mask + rows13, 26, 26, 16.0f);
    }
    // scale 52, stride 8
    {
        int ncells = B * 52 * 52;
        decode_scale_kernel<<<ncells / TPB, TPB>>>(
            out52, anc52, thr,
            boxes + (size_t)(rows13 + rows26) * 6, mask + rows13 + rows26,
            52, 52, 8.0f);
    }
}

// round 2
// speedup vs baseline: 1.2206x; 1.2206x over previous
#include <cuda_runtime.h>

// Fused YOLO decode over all 3 scales in a single launch.
// One thread per grid cell (b,h,w); 3 anchors per thread. Blocks are
// partitioned by scale (cell counts per scale are multiples of TPB, so no
// block straddles a scale boundary). Channel reads are coalesced
// (stride-HW layout); box rows staged through shared memory and written as
// one dense float2 block per CTA.

#define TPB 128

#define NBLK13 169    // 128*13*13/128
#define NBLK26 676    // 128*26*26/128
#define NBLK52 2704   // 128*52*52/128

__global__ __launch_bounds__(TPB)
void decode_fused_kernel(const float* __restrict__ in13,
                         const float* __restrict__ in26,
                         const float* __restrict__ in52,
                         const float* __restrict__ anc13,
                         const float* __restrict__ anc26,
                         const float* __restrict__ anc52,
                         const float* __restrict__ thresh_p,
                         float* __restrict__ boxes,   // [rowsTot, 6]
                         float* __restrict__ mask)    // [rowsTot]
{
    __shared__ float s[TPB * 18];

    // ---- block -> scale dispatch ----
    const float* in;
    const float* anchors;
    int W, HW;
    float stride;
    int blk;            // block index within this scale
    int rowbase;        // first box-row of this scale

    const int bid = blockIdx.x;
    if (bid < NBLK13) {
        in = in13; anchors = anc13; W = 13; HW = 169; stride = 32.0f;
        blk = bid;                    rowbase = 0;
    } else if (bid < NBLK13 + NBLK26) {
        in = in26; anchors = anc26; W = 26; HW = 676; stride = 16.0f;
        blk = bid - NBLK13;           rowbase = NBLK13 * TPB * 3;
    } else {
        in = in52; anchors = anc52; W = 52; HW = 2704; stride = 8.0f;
        blk = bid - (NBLK13 + NBLK26); rowbase = (NBLK13 + NBLK26) * TPB * 3;
    }

    const int t = threadIdx.x;
    const int cell = blk * TPB + t;          // cell index within this scale
    const int b  = cell / HW;
    const int cw = cell - b * HW;
    const int h  = cw / W;
    const int w  = cw - h * W;

    const float thr = __ldg(thresh_p);
    const float fw = (float)w;
    const float fh = (float)h;

    const float* base = in + (size_t)b * 45 * HW + cw;

    const float a0w = __ldg(anchors + 0), a0h = __ldg(anchors + 1);
    const float a1w = __ldg(anchors + 2), a1h = __ldg(anchors + 3);
    const float a2w = __ldg(anchors + 4), a2h = __ldg(anchors + 5);

    float row[3][6];
    float msk[3];

    #pragma unroll
    for (int a = 0; a < 3; ++a) {
        const float* p = base + (size_t)(a * 15) * HW;
        const float o0 = __ldg(p + 0 * (size_t)HW);
        const float o1 = __ldg(p + 1 * (size_t)HW);
        const float o2 = __ldg(p + 2 * (size_t)HW);
        const float o3 = __ldg(p + 3 * (size_t)HW);
        const float o4 = __ldg(p + 4 * (size_t)HW);

        // argmax over 10 class logits, first occurrence of max (strict >)
        float best = __ldg(p + 5 * (size_t)HW);
        int bi = 0;
        #pragma unroll
        for (int c = 1; c < 10; ++c) {
            float v = __ldg(p + (size_t)(5 + c) * HW);
            if (v > best) { best = v; bi = c; }
        }

        const float px = (fw + o1) * stride;
        const float py = (fh + o2) * stride;
        const float aw = (a == 0) ? a0w : (a == 1) ? a1w : a2w;
        const float ah = (a == 0) ? a0h : (a == 1) ? a1h : a2h;
        const float pw = aw * expf(o3);
        const float ph = ah * expf(o4);

        row[a][0] = o0;
        row[a][1] = px - 0.5f * pw;
        row[a][2] = py - 0.5f * ph;
        row[a][3] = px + 0.5f * pw;
        row[a][4] = py + 0.5f * ph;
        row[a][5] = (float)bi;
        msk[a] = (o0 > thr) ? 1.0f : 0.0f;
    }

    // mask: warp writes a dense 384B region (3 floats/thread, consecutive cells)
    const size_t mrow = (size_t)rowbase + (size_t)cell * 3;
    mask[mrow + 0] = msk[0];
    mask[mrow + 1] = msk[1];
    mask[mrow + 2] = msk[2];

    // boxes: stage 18 floats/thread, write 2304 contiguous floats per CTA
    #pragma unroll
    for (int a = 0; a < 3; ++a)
        #pragma unroll
        for (int j = 0; j < 6; ++j)
            s[t * 18 + a * 6 + j] = row[a][j];
    __syncthreads();

    float2* ob = (float2*)(boxes + (size_t)rowbase * 6 + (size_t)blk * TPB * 18);
    const float2* sb = (const float2*)s;
    #pragma unroll
    for (int k = 0; k < 9; ++k)
        ob[k * TPB + t] = sb[k * TPB + t];
}

extern "C" void kernel_launch(void* const* d_in, const int* in_sizes, int n_in,
                              void* d_out, int out_size)
{
    const float* out13 = (const float*)d_in[0];
    const float* out26 = (const float*)d_in[1];
    const float* out52 = (const float*)d_in[2];
    const float* anc13 = (const float*)d_in[3];
    const float* anc26 = (const float*)d_in[4];
    const float* anc52 = (const float*)d_in[5];
    const float* thr   = (const float*)d_in[6];

    float* out = (float*)d_out;

    const int rowsTot = (NBLK13 + NBLK26 + NBLK52) * TPB * 3;  // 1,362,816

    float* boxes = out;                       // [rowsTot, 6]
    float* mask  = out + (size_t)rowsTot * 6; // [rowsTot]

    decode_fused_kernel<<<NBLK13 + NBLK26 + NBLK52, TPB>>>(
        out13, out26, out52, anc13, anc26, anc52, thr, boxes, mask);
}

// round 3
// speedup vs baseline: 1.3113x; 1.0743x over previous
#include <cuda_runtime.h>

// Fused YOLO decode, single launch.
// Scales 52 & 26 (HW % 4 == 0): one thread per 4 consecutive cells, channel
// reads as float4 (LDG.128), 3 anchors/thread. Scale 13 (HW=169, odd):
// scalar path, 1 cell/thread. Boxes staged via smem -> dense STG.128.
// Output layout: boxes [N,6] in scale order 13,26,52, then mask [N].

#define TPB 128

#define VBLK52 676   // 128*52*52 cells / 4 / 128
#define VBLK26 169   // 128*26*26 cells / 4 / 128
#define SBLK13 169   // 128*13*13 cells / 128

#define ROWS13 64896      // 21632*3
#define ROWS26 259584     // 86528*3
#define ROWS52 1038336    // 346112*3
#define ROWBASE13 0
#define ROWBASE26 ROWS13
#define ROWBASE52 (ROWS13 + ROWS26)

__device__ __forceinline__ float f4c(const float4& q, int i) {
    // i is always a compile-time constant under full unrolling
    switch (i) {
        case 0: return q.x;
        case 1: return q.y;
        case 2: return q.z;
        default: return q.w;
    }
}

__global__ __launch_bounds__(TPB)
void decode_fused_kernel(const float* __restrict__ in13,
                         const float* __restrict__ in26,
                         const float* __restrict__ in52,
                         const float* __restrict__ anc13,
                         const float* __restrict__ anc26,
                         const float* __restrict__ anc52,
                         const float* __restrict__ thresh_p,
                         float* __restrict__ boxes,   // [rowsTot, 6]
                         float* __restrict__ mask)    // [rowsTot]
{
    __shared__ float s[4 * TPB * 18];   // 36864 B (vec path uses all of it)

    const int bid = blockIdx.x;
    const int t = threadIdx.x;
    const float thr = __ldg(thresh_p);

    if (bid < VBLK52 + VBLK26) {
        // ---------------- vectorized path (4 cells / thread) ----------------
        const float* in;
        const float* anchors;
        int W, HW;
        float stride;
        int blk;
        size_t rowbase;

        if (bid < VBLK52) {
            in = in52; anchors = anc52; W = 52; HW = 2704; stride = 8.0f;
            blk = bid;          rowbase = ROWBASE52;
        } else {
            in = in26; anchors = anc26; W = 26; HW = 676;  stride = 16.0f;
            blk = bid - VBLK52; rowbase = ROWBASE26;
        }

        const int cell0 = (blk * TPB + t) * 4;     // HW%4==0 -> no b/row crossing
        const int b   = cell0 / HW;
        const int cw0 = cell0 - b * HW;
        const int HW4 = HW >> 2;

        const float4* base = (const float4*)(in + (size_t)b * 45 * HW + cw0);

        float fw[4], fh[4];
        #pragma unroll
        for (int i = 0; i < 4; ++i) {
            const int cw = cw0 + i;
            const int h = cw / W;
            fw[i] = (float)(cw - h * W);
            fh[i] = (float)h;
        }

        const float a0w = __ldg(anchors + 0), a0h = __ldg(anchors + 1);
        const float a1w = __ldg(anchors + 2), a1h = __ldg(anchors + 3);
        const float a2w = __ldg(anchors + 4), a2h = __ldg(anchors + 5);

        float m[12];

        #pragma unroll
        for (int a = 0; a < 3; ++a) {
            const float4* p = base + (size_t)(a * 15) * HW4;
            float4 v[15];
            #pragma unroll
            for (int c = 0; c < 15; ++c)
                v[c] = __ldg(p + (size_t)c * HW4);

            const float aw = (a == 0) ? a0w : (a == 1) ? a1w : a2w;
            const float ah = (a == 0) ? a0h : (a == 1) ? a1h : a2h;

            #pragma unroll
            for (int i = 0; i < 4; ++i) {
                const float o0 = f4c(v[0], i);
                const float o1 = f4c(v[1], i);
                const float o2 = f4c(v[2], i);
                const float o3 = f4c(v[3], i);
                const float o4 = f4c(v[4], i);

                float best = f4c(v[5], i);
                int bi = 0;
                #pragma unroll
                for (int c = 1; c < 10; ++c) {
                    const float q = f4c(v[5 + c], i);
                    if (q > best) { best = q; bi = c; }
                }

                const float px = (fw[i] + o1) * stride;
                const float py = (fh[i] + o2) * stride;
                const float pw = aw * __expf(o3);
                const float ph = ah * __expf(o4);

                const int lc = t * 4 + i;
                float* r = s + lc * 18 + a * 6;
                r[0] = o0;
                r[1] = px - 0.5f * pw;
                r[2] = py - 0.5f * ph;
                r[3] = px + 0.5f * pw;
                r[4] = py + 0.5f * ph;
                r[5] = (float)bi;

                m[i * 3 + a] = (o0 > thr) ? 1.0f : 0.0f;
            }
        }

        // mask: 12 contiguous floats per thread -> 3 STG.128
        float4* mp = (float4*)(mask + rowbase + (size_t)blk * TPB * 12 + t * 12);
        mp[0] = make_float4(m[0], m[1], m[2], m[3]);
        mp[1] = make_float4(m[4], m[5], m[6], m[7]);
        mp[2] = make_float4(m[8], m[9], m[10], m[11]);

        __syncthreads();

        // boxes: 9216 floats per CTA = 2304 float4, 18 per thread, coalesced
        float4* ob = (float4*)(boxes + rowbase * 6 + (size_t)blk * TPB * 72);
        const float4* sb = (const float4*)s;
        #pragma unroll
        for (int k = 0; k < 18; ++k)
            ob[k * TPB + t] = sb[k * TPB + t];

    } else {
        // ---------------- scalar path: scale 13 ----------------
        const int blk = bid - (VBLK52 + VBLK26);
        const int HW = 169, W = 13;
        const float stride = 32.0f;

        const int cell = blk * TPB + t;
        const int b  = cell / HW;
        const int cw = cell - b * HW;
        const int h  = cw / W;
        const int w  = cw - h * W;

        const float fw = (float)w;
        const float fh = (float)h;
        const float* base = in13 + (size_t)b * 45 * HW + cw;

        const float a0w = __ldg(anc13 + 0), a0h = __ldg(anc13 + 1);
        const float a1w = __ldg(anc13 + 2), a1h = __ldg(anc13 + 3);
        const float a2w = __ldg(anc13 + 4), a2h = __ldg(anc13 + 5);

        float msk[3];

        #pragma unroll
        for (int a = 0; a < 3; ++a) {
            const float* p = base + (size_t)(a * 15) * HW;
            float c0 = __ldg(p + 0 * (size_t)HW);
            float c1 = __ldg(p + 1 * (size_t)HW);
            float c2 = __ldg(p + 2 * (size_t)HW);
            float c3 = __ldg(p + 3 * (size_t)HW);
            float c4 = __ldg(p + 4 * (size_t)HW);

            float best = __ldg(p + 5 * (size_t)HW);
            int bi = 0;
            #pragma unroll
            for (int c = 1; c < 10; ++c) {
                const float q = __ldg(p + (size_t)(5 + c) * HW);
                if (q > best) { best = q; bi = c; }
            }

            const float px = (fw + c1) * stride;
            const float py = (fh + c2) * stride;
            const float aw = (a == 0) ? a0w : (a == 1) ? a1w : a2w;
            const float ah = (a == 0) ? a0h : (a == 1) ? a1h : a2h;
            const float pw = aw * __expf(c3);
            const float ph = ah * __expf(c4);

            float* r = s + t * 18 + a * 6;
            r[0] = c0;
            r[1] = px - 0.5f * pw;
            r[2] = py - 0.5f * ph;
            r[3] = px + 0.5f * pw;
            r[4] = py + 0.5f * ph;
            r[5] = (float)bi;
            msk[a] = (c0 > thr) ? 1.0f : 0.0f;
        }

        const size_t mrow = (size_t)ROWBASE13 + (size_t)cell * 3;
        mask[mrow + 0] = msk[0];
        mask[mrow + 1] = msk[1];
        mask[mrow + 2] = msk[2];

        __syncthreads();

        float2* ob = (float2*)(boxes + (size_t)ROWBASE13 * 6 + (size_t)blk * TPB * 18);
        const float2* sb = (const float2*)s;
        #pragma unroll
        for (int k = 0; k < 9; ++k)
            ob[k * TPB + t] = sb[k * TPB + t];
    }
}

extern "C" void kernel_launch(void* const* d_in, const int* in_sizes, int n_in,
                              void* d_out, int out_size)
{
    const float* out13 = (const float*)d_in[0];
    const float* out26 = (const float*)d_in[1];
    const float* out52 = (const float*)d_in[2];
    const float* anc13 = (const float*)d_in[3];
    const float* anc26 = (const float*)d_in[4];
    const float* anc52 = (const float*)d_in[5];
    const float* thr   = (const float*)d_in[6];

    float* out = (float*)d_out;
    const int rowsTot = ROWS13 + ROWS26 + ROWS52;   // 1,362,816

    float* boxes = out;                       // [rowsTot, 6]
    float* mask  = out + (size_t)rowsTot * 6; // [rowsTot]

    decode_fused_kernel<<<VBLK52 + VBLK26 + SBLK13, TPB>>>(
        out13, out26, out52, anc13, anc26, anc52, thr, boxes, mask);
}